// round 1
// baseline (speedup 1.0000x reference)
#include <cuda_runtime.h>

// ---------------------------------------------------------------------------
// Untied LeNet, B=1024. All intermediates stored batch-minor for coalescing.
// ---------------------------------------------------------------------------

#define BATCH 1024

__device__ float g_xT[3 * 32 * 32 * BATCH];   // (C,H,W,B)      12.6 MB
__device__ float g_h1[6 * 14 * 14 * BATCH];   // (O1,Ho,Wo,B)    4.8 MB
__device__ float g_h2[16 * 25 * BATCH];       // (O2,5,5,B)      1.6 MB
__device__ float g_h3[BATCH * 120];           // (B,120)         0.5 MB

// ---------------------------------------------------------------------------
// Kernel 0: transpose x (B, 3072) -> xT (3072, B)
// ---------------------------------------------------------------------------
__global__ void k_transpose(const float* __restrict__ x) {
    __shared__ float tile[32][33];
    int f0 = blockIdx.x * 32;
    int b0 = blockIdx.y * 32;
    int tx = threadIdx.x, ty = threadIdx.y;
#pragma unroll
    for (int i = 0; i < 4; i++)
        tile[ty + i * 8][tx] = x[(b0 + ty + i * 8) * 3072 + f0 + tx];
    __syncthreads();
#pragma unroll
    for (int i = 0; i < 4; i++)
        g_xT[(f0 + ty + i * 8) * BATCH + b0 + tx] = tile[tx][ty + i * 8];
}

// ---------------------------------------------------------------------------
// Kernel A: untied conv1 (5x5, 3->6, out 28x28) + relu + 2x2 maxpool -> (6,14,14,B)
// grid (196 pooled positions, 4 batch chunks), block 256 (one batch item/thread)
// ---------------------------------------------------------------------------
__global__ void __launch_bounds__(256) k_conv1(const float* __restrict__ w1,
                                               const float* __restrict__ b1) {
    __shared__ float w_s[1800];   // [s][o][c][25]
    __shared__ float bias_s[24];  // [s][o]
    int pos = blockIdx.x;
    int oh = pos / 14, ow = pos % 14;
    int tid = threadIdx.x;

    for (int l = tid; l < 1800; l += 256) {
        int s = l / 450, r = l % 450;
        int o = r / 75, r2 = r % 75;
        int c = r2 / 25, kk = r2 % 25;
        int y = 2 * oh + (s >> 1), x2 = 2 * ow + (s & 1);
        w_s[l] = w1[(((o * 3 + c) * 28 + y) * 28 + x2) * 25 + kk];
    }
    if (tid < 24) {
        int s = tid / 6, o = tid % 6;
        int y = 2 * oh + (s >> 1), x2 = 2 * ow + (s & 1);
        bias_s[tid] = b1[(o * 28 + y) * 28 + x2];
    }
    __syncthreads();

    int b = blockIdx.y * 256 + tid;
    float acc[4][6];
#pragma unroll
    for (int s = 0; s < 4; s++)
#pragma unroll
        for (int o = 0; o < 6; o++) acc[s][o] = bias_s[s * 6 + o];

    for (int c = 0; c < 3; c++) {
        float p[6][6];
#pragma unroll
        for (int iy = 0; iy < 6; iy++)
#pragma unroll
            for (int ix = 0; ix < 6; ix++)
                p[iy][ix] = g_xT[((c * 32 + 2 * oh + iy) * 32 + 2 * ow + ix) * BATCH + b];
#pragma unroll
        for (int s = 0; s < 4; s++) {
            int sy = s >> 1, sx = s & 1;
#pragma unroll
            for (int o = 0; o < 6; o++) {
                const float* wp = &w_s[(s * 6 + o) * 75 + c * 25];
                float a = acc[s][o];
#pragma unroll
                for (int ky = 0; ky < 5; ky++)
#pragma unroll
                    for (int kx = 0; kx < 5; kx++)
                        a += p[sy + ky][sx + kx] * wp[ky * 5 + kx];
                acc[s][o] = a;
            }
        }
    }
#pragma unroll
    for (int o = 0; o < 6; o++) {
        float m = fmaxf(fmaxf(acc[0][o], acc[1][o]), fmaxf(acc[2][o], acc[3][o]));
        g_h1[((o * 14 + oh) * 14 + ow) * BATCH + b] = fmaxf(m, 0.f);
    }
}

// ---------------------------------------------------------------------------
// Kernel B: untied conv2 (5x5, 6->16, out 10x10) + relu + 2x2 maxpool -> (16,5,5,B)
// grid (25 positions, 2 channel groups of 8, 8 batch chunks), block 128
// ---------------------------------------------------------------------------
__global__ void __launch_bounds__(128) k_conv2(const float* __restrict__ w2,
                                               const float* __restrict__ b2) {
    __shared__ float w_s[4800];   // [s][ol][c][25]
    __shared__ float bias_s[32];  // [s][ol]
    int pos = blockIdx.x;
    int oh = pos / 5, ow = pos % 5;
    int og = blockIdx.y;
    int tid = threadIdx.x;

    for (int l = tid; l < 4800; l += 128) {
        int s = l / 1200, r = l % 1200;
        int ol = r / 150, r2 = r % 150;
        int c = r2 / 25, kk = r2 % 25;
        int o = og * 8 + ol;
        int y = 2 * oh + (s >> 1), x2 = 2 * ow + (s & 1);
        w_s[l] = w2[(((o * 6 + c) * 10 + y) * 10 + x2) * 25 + kk];
    }
    if (tid < 32) {
        int s = tid / 8, ol = tid % 8;
        int o = og * 8 + ol;
        int y = 2 * oh + (s >> 1), x2 = 2 * ow + (s & 1);
        bias_s[tid] = b2[(o * 10 + y) * 10 + x2];
    }
    __syncthreads();

    int b = blockIdx.z * 128 + tid;
    float acc[4][8];
#pragma unroll
    for (int s = 0; s < 4; s++)
#pragma unroll
        for (int ol = 0; ol < 8; ol++) acc[s][ol] = bias_s[s * 8 + ol];

    for (int c = 0; c < 6; c++) {
        float p[6][6];
#pragma unroll
        for (int iy = 0; iy < 6; iy++)
#pragma unroll
            for (int ix = 0; ix < 6; ix++)
                p[iy][ix] = g_h1[((c * 14 + 2 * oh + iy) * 14 + 2 * ow + ix) * BATCH + b];
#pragma unroll
        for (int s = 0; s < 4; s++) {
            int sy = s >> 1, sx = s & 1;
#pragma unroll
            for (int ol = 0; ol < 8; ol++) {
                const float* wp = &w_s[(s * 8 + ol) * 150 + c * 25];
                float a = acc[s][ol];
#pragma unroll
                for (int ky = 0; ky < 5; ky++)
#pragma unroll
                    for (int kx = 0; kx < 5; kx++)
                        a += p[sy + ky][sx + kx] * wp[ky * 5 + kx];
                acc[s][ol] = a;
            }
        }
    }
#pragma unroll
    for (int ol = 0; ol < 8; ol++) {
        float m = fmaxf(fmaxf(acc[0][ol], acc[1][ol]), fmaxf(acc[2][ol], acc[3][ol]));
        int o = og * 8 + ol;
        g_h2[((o * 5 + oh) * 5 + ow) * BATCH + b] = fmaxf(m, 0.f);
    }
}

// ---------------------------------------------------------------------------
// Kernel C: conv3 == GEMM out(1024,120) = h2(1024,400) @ w3(120,400)^T + b3, relu
// grid (32 batch tiles of 32, 15 out-channel groups of 8), block 256 = 32b x 8o
// ---------------------------------------------------------------------------
__global__ void __launch_bounds__(256) k_conv3(const float* __restrict__ w3,
                                               const float* __restrict__ b3) {
    __shared__ float A_s[200 * 32];  // K-chunk x batch
    __shared__ float W_s[8 * 400];
    int tid = threadIdx.x;
    int b0 = blockIdx.x * 32;
    int og = blockIdx.y;

    for (int l = tid; l < 3200; l += 256)
        W_s[l] = w3[og * 3200 + l];  // (og*8+ol)*400 + k

    int blocal = tid & 31, olocal = tid >> 5;
    int o = og * 8 + olocal;
    float acc = b3[o];

    for (int kc = 0; kc < 400; kc += 200) {
        __syncthreads();
        for (int l = tid; l < 6400; l += 256)
            A_s[l] = g_h2[(kc + (l >> 5)) * BATCH + b0 + (l & 31)];
        __syncthreads();
#pragma unroll 10
        for (int k = 0; k < 200; k++)
            acc += A_s[k * 32 + blocal] * W_s[olocal * 400 + kc + k];
    }
    g_h3[(b0 + blocal) * 120 + o] = fmaxf(acc, 0.f);
}

// ---------------------------------------------------------------------------
// Kernel D: fused FC2 (120->84, relu) + FC3 (84->10). One warp per batch item.
// grid 128, block 256 (8 warps)
// ---------------------------------------------------------------------------
__global__ void __launch_bounds__(256) k_fc(const float* __restrict__ fc2_w,
                                            const float* __restrict__ fc2_b,
                                            const float* __restrict__ fc3_w,
                                            const float* __restrict__ fc3_b,
                                            float* __restrict__ out) {
    __shared__ float w2_s[84 * 121];  // stride 121: odd => conflict-free
    __shared__ float h_s[8][120];
    __shared__ float h84_s[8][84];
    int tid = threadIdx.x;

    for (int l = tid; l < 84 * 120; l += 256) {
        int r = l / 120, c = l % 120;
        w2_s[r * 121 + c] = fc2_w[l];
    }
    __syncthreads();

    int w = tid >> 5, lane = tid & 31;
    int b = blockIdx.x * 8 + w;

#pragma unroll
    for (int m = 0; m < 4; m++) {
        int k = lane + 32 * m;
        if (k < 120) h_s[w][k] = g_h3[b * 120 + k];
    }
    __syncwarp();

#pragma unroll
    for (int m = 0; m < 3; m++) {
        int jj = lane + 32 * m;
        if (jj < 84) {
            float a = fc2_b[jj];
#pragma unroll
            for (int k = 0; k < 120; k++)
                a += h_s[w][k] * w2_s[jj * 121 + k];
            h84_s[w][jj] = fmaxf(a, 0.f);
        }
    }
    __syncwarp();

    if (lane < 10) {
        float a = fc3_b[lane];
#pragma unroll
        for (int k = 0; k < 84; k++)
            a += h84_s[w][k] * fc3_w[lane * 84 + k];
        out[b * 10 + lane] = a;
    }
}

// ---------------------------------------------------------------------------
extern "C" void kernel_launch(void* const* d_in, const int* in_sizes, int n_in,
                              void* d_out, int out_size) {
    const float* x    = (const float*)d_in[0];
    const float* w1   = (const float*)d_in[1];
    const float* b1   = (const float*)d_in[2];
    const float* w2   = (const float*)d_in[3];
    const float* b2   = (const float*)d_in[4];
    const float* w3   = (const float*)d_in[5];
    const float* b3   = (const float*)d_in[6];
    const float* fc2w = (const float*)d_in[7];
    const float* fc2b = (const float*)d_in[8];
    const float* fc3w = (const float*)d_in[9];
    const float* fc3b = (const float*)d_in[10];
    float* out = (float*)d_out;

    k_transpose<<<dim3(96, 32), dim3(32, 8)>>>(x);
    k_conv1<<<dim3(196, 4), 256>>>(w1, b1);
    k_conv2<<<dim3(25, 2, 8), 128>>>(w2, b2);
    k_conv3<<<dim3(32, 15), 256>>>(w3, b3);
    k_fc<<<128, 256>>>(fc2w, fc2b, fc3w, fc3b, out);
}